// round 15
// baseline (speedup 1.0000x reference)
#include <cuda_runtime.h>
#include <cuda_bf16.h>
#include <cuda_fp16.h>
#include <math.h>
#include <stdint.h>

// Problem constants
#define BATCH 2048      // B*T
#define NAG   16
#define NACT  20
#define DDIM  128
#define NSAMP 32
#define EDIM  64
#define HDIM  256
#define W1N   2560      // E*2*A
#define CATN  640       // 256(h1a)+256(hf)+64(b1)+64(vh)

// ---------------- scratch (device globals) ----------------
__device__ float g_out0[BATCH * CATN];
__device__ __half g_Ahi[BATCH * HDIM];      // h1a fp16 hi
__device__ __half g_Alo[BATCH * HDIM];      // h1a fp16 lo
__device__ __half g_Bhi[W1N * HDIM];        // W1b^T fp16 (single rounding)
__device__ __half g_w1h[BATCH * W1N];       // |w1| in fp16 (halved round-trip)
__device__ float g_wf [BATCH * EDIM];
__device__ float g_coal[BATCH * NAG * NACT];

// ===================== PTX helpers =====================
__device__ __forceinline__ uint32_t smem_to_u32(const void* p) {
    uint32_t a;
    asm("{ .reg .u64 t; cvta.to.shared.u64 t, %1; cvt.u32.u64 %0, t; }" : "=r"(a) : "l"(p));
    return a;
}
#define LDMATRIX_X4(r, a) \
    asm volatile("ldmatrix.sync.aligned.m8n8.x4.shared.b16 {%0,%1,%2,%3}, [%4];" \
        : "=r"((r)[0]), "=r"((r)[1]), "=r"((r)[2]), "=r"((r)[3]) : "r"(a))
#define MMA16816H(c, a, b0, b1) \
    asm volatile("mma.sync.aligned.m16n8k16.row.col.f32.f16.f16.f32 " \
        "{%0,%1,%2,%3},{%4,%5,%6,%7},{%8,%9},{%0,%1,%2,%3};" \
        : "+f"((c)[0]), "+f"((c)[1]), "+f"((c)[2]), "+f"((c)[3]) \
        : "r"((a)[0]), "r"((a)[1]), "r"((a)[2]), "r"((a)[3]), "r"(b0), "r"(b1))
#define CP_ASYNC16(dst, src) \
    asm volatile("cp.async.cg.shared.global [%0], [%1], 16;" :: "r"(dst), "l"(src))
#define CP_COMMIT() asm volatile("cp.async.commit_group;" ::: "memory")
#define CP_WAIT1()  asm volatile("cp.async.wait_group 1;" ::: "memory")
#define CP_WAIT0()  asm volatile("cp.async.wait_group 0;" ::: "memory")

// ======================================================================
// STAGE 1: gemm0 (320) + trans_split (640), 66 KB dynamic smem
// ======================================================================
#define S1_GEMM0_BLKS 320
#define S1_TRANS_BLKS 640
#define S1_TOTAL (S1_GEMM0_BLKS + S1_TRANS_BLKS)
#define SMEM_S1  66560

__device__ __forceinline__ void gemm0_block(
    int bx, char* smraw, const float* __restrict__ states,
    const float* __restrict__ W1a, const float* __restrict__ b1a,
    const float* __restrict__ Wfa, const float* __restrict__ bfa,
    const float* __restrict__ Wb,  const float* __restrict__ bb,
    const float* __restrict__ Wv1, const float* __restrict__ bv1)
{
    float* As = (float*)smraw;                   // [64][132]
    float* Bs = (float*)(smraw + 33792);         // [128][64]

    const int tid = threadIdx.x;
    const int n0 = (bx % 10) * 64;
    const int m0 = (bx / 10) * 64;
    const int tx = tid & 15, ty = tid >> 4;

    const float* Bsrc; const float* bias; int ldb; int nc0;
    if      (n0 < 256) { Bsrc = W1a; bias = b1a; ldb = 256; nc0 = n0; }
    else if (n0 < 512) { Bsrc = Wfa; bias = bfa; ldb = 256; nc0 = n0 - 256; }
    else if (n0 < 576) { Bsrc = Wb;  bias = bb;  ldb = 64;  nc0 = 0; }
    else               { Bsrc = Wv1; bias = bv1; ldb = 64;  nc0 = 0; }

#pragma unroll
    for (int j = 0; j < 8; j++) {
        int idx = tid + j * 256;
        int k = idx >> 4, c = idx & 15;
        CP_ASYNC16(smem_to_u32(&Bs[k * 64 + c * 4]),
                   Bsrc + (size_t)k * ldb + nc0 + c * 4);
    }
    CP_COMMIT();

#pragma unroll
    for (int j = 0; j < 8; j++) {
        int idx = tid + j * 256;
        int kg = idx & 31, m = idx >> 5;
        float4 v = *(const float4*)(states + (size_t)(m0 + m) * DDIM + kg * 4);
        *(float4*)&As[m * 132 + kg * 4] = v;
    }
    CP_WAIT0();
    __syncthreads();

    float acc[4][4];
#pragma unroll
    for (int r = 0; r < 4; r++)
#pragma unroll
        for (int j = 0; j < 4; j++) acc[r][j] = 0.f;

#pragma unroll 8
    for (int kk = 0; kk < 128; kk++) {
        float av[4];
#pragma unroll
        for (int r = 0; r < 4; r++) av[r] = As[(ty * 4 + r) * 132 + kk];
        float4 bv = *(const float4*)&Bs[kk * 64 + tx * 4];
        float bw[4] = {bv.x, bv.y, bv.z, bv.w};
#pragma unroll
        for (int r = 0; r < 4; r++)
#pragma unroll
            for (int j = 0; j < 4; j++)
                acc[r][j] += av[r] * bw[j];
    }

    const bool do_relu = (n0 != 512);
    float bs[4];
#pragma unroll
    for (int j = 0; j < 4; j++) bs[j] = bias[nc0 + tx * 4 + j];

#pragma unroll
    for (int r = 0; r < 4; r++) {
        int m = m0 + ty * 4 + r;
        float4 o;
        float* po = &o.x;
#pragma unroll
        for (int j = 0; j < 4; j++) {
            float v = acc[r][j] + bs[j];
            if (do_relu) v = fmaxf(v, 0.f);
            po[j] = v;
        }
        *(float4*)&g_out0[(size_t)m * CATN + n0 + tx * 4] = o;
        if (n0 < 256) {
            __half h[4]; float lo[4];
#pragma unroll
            for (int j = 0; j < 4; j++) {
                h[j] = __float2half(po[j]);
                lo[j] = po[j] - __half2float(h[j]);
            }
            size_t base = (size_t)m * HDIM + n0 + tx * 4;
            *(__half2*)&g_Ahi[base]     = __halves2half2(h[0], h[1]);
            *(__half2*)&g_Ahi[base + 2] = __halves2half2(h[2], h[3]);
            *(__half2*)&g_Alo[base]     = __halves2half2(__float2half(lo[0]), __float2half(lo[1]));
            *(__half2*)&g_Alo[base + 2] = __halves2half2(__float2half(lo[2]), __float2half(lo[3]));
        }
    }
}

__device__ __forceinline__ void trans_block(int t, char* smraw, const float* __restrict__ W1b)
{
    float* ts = (float*)smraw;      // [32][33]
    int n0 = (t % 80) * 32, k0 = (t / 80) * 32;
    int tx = threadIdx.x & 31, ty = threadIdx.x >> 5;
#pragma unroll
    for (int r = 0; r < 4; r++)
        ts[(ty * 4 + r) * 33 + tx] = W1b[(size_t)(k0 + ty * 4 + r) * W1N + n0 + tx];
    __syncthreads();
#pragma unroll
    for (int r = 0; r < 4; r++) {
        int n = n0 + ty * 4 + r, k = k0 + tx;
        g_Bhi[(size_t)n * HDIM + k] = __float2half(ts[tx * 33 + ty * 4 + r]);
    }
}

__global__ void __launch_bounds__(256)
stage1_kernel(const float* __restrict__ states,
              const float* __restrict__ W1a, const float* __restrict__ b1a,
              const float* __restrict__ Wfa, const float* __restrict__ bfa,
              const float* __restrict__ Wb,  const float* __restrict__ bb,
              const float* __restrict__ Wv1, const float* __restrict__ bv1,
              const float* __restrict__ W1b)
{
    extern __shared__ __align__(16) char smd[];
    const int bx = blockIdx.x;
    if (bx < S1_GEMM0_BLKS)
        gemm0_block(bx, smd, states, W1a, b1a, Wfa, bfa, Wb, bb, Wv1, bv1);
    else
        trans_block(bx - S1_GEMM0_BLKS, smd, W1b);
}

// ======================================================================
// coal standalone (small smem, high occupancy)
// ======================================================================
__global__ void __launch_bounds__(256)
coal_kernel(const float* __restrict__ actions, const int* __restrict__ gc)
{
    __shared__ int   gcs[NSAMP * NAG];
    __shared__ int   inv[NSAMP * NAG];
    __shared__ float act_s[NAG * NACT];
    __shared__ float Ws[NAG * NAG];

    const int b = blockIdx.x;
    const int tid = threadIdx.x;

    for (int idx = tid; idx < 512; idx += 256)
        gcs[idx] = gc[b * 512 + idx];
    for (int idx = tid; idx < 320; idx += 256)
        act_s[idx] = actions[b * 320 + idx];
    __syncthreads();

    {
        int s = tid >> 4, pos = tid & 15;
        inv[s * 16 + gcs[s * 16 + pos]] = pos;
        inv[(s + 16) * 16 + gcs[(s + 16) * 16 + pos]] = pos;
    }
    __syncthreads();

    {
        int i = tid >> 4, m = tid & 15;
        int w = 0;
#pragma unroll
        for (int s = 0; s < 32; s++) {
            int gi = gcs[s * 16 + i];
            int pm = inv[s * 16 + m];
            w += (pm < gi) ? gi : 0;
        }
        Ws[i * 16 + m] = (float)w;
    }
    __syncthreads();

    {
        int i = tid >> 4, c = tid & 15;
        for (int a = c; a < NACT; a += 16) {
            float sum = 0.f;
#pragma unroll
            for (int m = 0; m < 16; m++)
                sum += Ws[i * 16 + m] * act_s[m * NACT + a];
            g_coal[b * 320 + i * NACT + a] = sum * (1.f / 512.f);
        }
    }
}

// ======================================================================
// STAGE 2: wf (128, first) + hmma 128x128 (320 blocks), fp16 2-product
// ======================================================================
#define T_ROWB   80
#define T_BYTES  (128 * T_ROWB)
#define STAGE_B  (3 * T_BYTES)    // Ah, Al, Bh -> 30720
#define SMEM_S2  (2 * STAGE_B)    // 61440

__device__ __forceinline__ void hmma_block(int bx, char* sm, const float* __restrict__ b1b)
{
    const int tid = threadIdx.x;
    const int wid = tid >> 5, lane = tid & 31;
    const int n0 = (bx % 20) * 128;
    const int m0 = (bx / 20) * 128;
    const int wm = (wid >> 2) * 64;
    const int wn = (wid & 3) * 32;

    float acc[4][4][4];
#pragma unroll
    for (int r = 0; r < 4; r++)
#pragma unroll
        for (int g = 0; g < 4; g++)
#pragma unroll
            for (int c = 0; c < 4; c++) acc[r][g][c] = 0.f;

    const __half* srcs[3] = {g_Ahi, g_Alo, g_Bhi};

    auto load_stage = [&](int s, int k0) {
#pragma unroll
        for (int t = 0; t < 3; t++) {
            const int r0 = (t < 2) ? m0 : n0;
            const __half* src = srcs[t];
            char* dstb = sm + s * STAGE_B + t * T_BYTES;
#pragma unroll
            for (int j = 0; j < 2; j++) {
                int idx = tid + j * 256;
                int row = idx >> 2, c = idx & 3;
                CP_ASYNC16(smem_to_u32(dstb + row * T_ROWB + c * 16),
                           (const char*)(src + (size_t)(r0 + row) * HDIM + k0) + c * 16);
            }
        }
    };

    load_stage(0, 0);
    CP_COMMIT();

    for (int kc = 0; kc < 8; kc++) {
        if (kc < 7) { load_stage((kc + 1) & 1, (kc + 1) * 32); CP_COMMIT(); CP_WAIT1(); }
        else        { CP_WAIT0(); }
        __syncthreads();

        char* Ah = sm + (kc & 1) * STAGE_B;
        char* Al = Ah + T_BYTES;
        char* Bh = Ah + 2 * T_BYTES;

#pragma unroll
        for (int ks = 0; ks < 2; ks++) {
            const int kb = ks * 32;
            uint32_t ah[4][4], al[4][4], bh[2][4];
            const int arow = wm + (lane & 15);
            const int akb  = kb + (lane >> 4) * 16;
#pragma unroll
            for (int r = 0; r < 4; r++) {
                LDMATRIX_X4(ah[r], smem_to_u32(Ah + (arow + r * 16) * T_ROWB + akb));
                LDMATRIX_X4(al[r], smem_to_u32(Al + (arow + r * 16) * T_ROWB + akb));
            }
            const int brow = wn + (lane & 7) + (lane >> 4) * 8;
            const int bkb  = kb + ((lane >> 3) & 1) * 16;
#pragma unroll
            for (int g = 0; g < 2; g++) {
                LDMATRIX_X4(bh[g], smem_to_u32(Bh + (brow + g * 16) * T_ROWB + bkb));
            }
#pragma unroll
            for (int r = 0; r < 4; r++)
#pragma unroll
                for (int g = 0; g < 4; g++) {
                    uint32_t b0h = bh[g >> 1][(g & 1) * 2], b1h = bh[g >> 1][(g & 1) * 2 + 1];
                    MMA16816H(acc[r][g], ah[r], b0h, b1h);   // ah*bh
                    MMA16816H(acc[r][g], al[r], b0h, b1h);   // al*bh
                }
        }
        __syncthreads();
    }

    const int mrow  = m0 + wm + (lane >> 2);
    const int ncol0 = n0 + wn + (lane & 3) * 2;
#pragma unroll
    for (int g = 0; g < 4; g++) {
        const int n = ncol0 + g * 8;
        float2 bias = *(const float2*)&b1b[n];
#pragma unroll
        for (int r = 0; r < 4; r++) {
            const int m = mrow + r * 16;
            __half2 o0 = __floats2half2_rn(fabsf(acc[r][g][0] + bias.x),
                                           fabsf(acc[r][g][1] + bias.y));
            __half2 o1 = __floats2half2_rn(fabsf(acc[r][g][2] + bias.x),
                                           fabsf(acc[r][g][3] + bias.y));
            *(__half2*)&g_w1h[(size_t)m * W1N + n]       = o0;
            *(__half2*)&g_w1h[(size_t)(m + 8) * W1N + n] = o1;
        }
    }
}

__device__ __forceinline__ void wf_block(int wb, char* sm,
    const float* __restrict__ Wfb, const float* __restrict__ bfb)
{
    float* As = (float*)sm;             // [2][16][36]
    float* Bs = (float*)(sm + 4608);    // [2][32][64]
    const int tid = threadIdx.x;
    const int m0 = wb * 16;
    const int tx = tid & 15, ty = tid >> 4;

    auto load_stage = [&](int s, int k0) {
        if (tid < 128) {
            int row = tid >> 3, c = tid & 7;
            CP_ASYNC16(smem_to_u32(&As[s * 576 + row * 36 + c * 4]),
                       g_out0 + (size_t)(m0 + row) * CATN + 256 + k0 + c * 4);
        }
#pragma unroll
        for (int j = 0; j < 2; j++) {
            int idx = tid * 2 + j;
            int k = idx >> 4, c = idx & 15;
            CP_ASYNC16(smem_to_u32(&Bs[s * 2048 + k * 64 + c * 4]),
                       Wfb + (size_t)(k0 + k) * EDIM + c * 4);
        }
    };

    float acc[4] = {0.f, 0.f, 0.f, 0.f};
    load_stage(0, 0);
    CP_COMMIT();

    for (int c = 0; c < 8; c++) {
        if (c < 7) { load_stage((c + 1) & 1, (c + 1) * 32); CP_COMMIT(); CP_WAIT1(); }
        else       { CP_WAIT0(); }
        __syncthreads();
        const int buf = c & 1;
#pragma unroll
        for (int kk = 0; kk < 32; kk++) {
            float a = As[buf * 576 + ty * 36 + kk];
            float4 bv = *(const float4*)&Bs[buf * 2048 + kk * 64 + tx * 4];
            acc[0] += a * bv.x; acc[1] += a * bv.y;
            acc[2] += a * bv.z; acc[3] += a * bv.w;
        }
        __syncthreads();
    }

    float4 bsv = *(const float4*)&bfb[tx * 4];
    float4 o;
    o.x = fabsf(acc[0] + bsv.x);
    o.y = fabsf(acc[1] + bsv.y);
    o.z = fabsf(acc[2] + bsv.z);
    o.w = fabsf(acc[3] + bsv.w);
    *(float4*)&g_wf[(size_t)(m0 + ty) * EDIM + tx * 4] = o;
}

__global__ void __launch_bounds__(256)
stage2_kernel(const float* __restrict__ b1b,
              const float* __restrict__ Wfb, const float* __restrict__ bfb)
{
    extern __shared__ char sm[];
    const int bx = blockIdx.x;
    if (bx < 128) wf_block(bx, sm, Wfb, bfb);
    else          hmma_block(bx - 128, sm, b1b);
}

// ======================================================================
// STAGE 3: final mix, register-tiled, 4 rows/block, w1 in fp16 smem
// ======================================================================
// float-slot offsets (w1h occupies 5120 float slots = 20480 B of halfs)
#define FS_W1    0
#define FS_INST  5120     // [4][40][16]
#define FS_B1    7680     // [4][64]
#define FS_WF    7936     // [4][64]
#define FS_VP    8192     // [4][2]
#define FS_YROW  8200     // [4][16]
#define FINAL_SMEM ((8264 + 24) * 4)   // 33152 bytes

__global__ void __launch_bounds__(256)
final_kernel(const float* __restrict__ actions, const float* __restrict__ Wv2,
             const float* __restrict__ bv2, const float* __restrict__ agent_qs,
             float* __restrict__ q_out, float* __restrict__ w_out)
{
    extern __shared__ __align__(16) float fs[];
    __half* w1h  = (__half*)(fs + FS_W1);
    float* insT = fs + FS_INST;
    float* b1c  = fs + FS_B1;
    float* wfc  = fs + FS_WF;
    float* vpart= fs + FS_VP;
    float* yrow = fs + FS_YROW;

    const int tid = threadIdx.x;
    const int b0 = blockIdx.x * 4;

    // w1: 4 rows x 2560 halves = 20480 B = 1280 x 16B chunks, 5/thread
    {
        const __half* src0 = g_w1h + (size_t)b0 * W1N;
#pragma unroll
        for (int j = 0; j < 5; j++) {
            int idx = tid + j * 256;
            CP_ASYNC16(smem_to_u32((char*)w1h + idx * 16), (const char*)src0 + idx * 16);
        }
        CP_COMMIT();
    }

    const int r  = tid >> 6;
    const int u  = tid & 63;
    const int ig = u >> 4;
    const int eg = u & 15;
    const int i0 = ig * 4, e0 = eg * 4;

#pragma unroll
    for (int j = 0; j < 10; j++) {
        int idx = tid + j * 256;
        int rr = idx / 640, rem = idx % 640;
        int k = rem >> 4, i = rem & 15;
        int bb = b0 + rr;
        float v = (k < 20) ? g_coal[bb * 320 + i * 20 + k]
                           : actions[bb * 320 + i * 20 + (k - 20)];
        insT[rr * 640 + k * 16 + i] = v;
    }
    {
        const int brow = b0 + r;
        int e = u;
        b1c[r * 64 + e] = g_out0[(size_t)brow * CATN + 512 + e];
        wfc[r * 64 + e] = g_wf[(size_t)brow * EDIM + e];
        float pv = g_out0[(size_t)brow * CATN + 576 + e] * Wv2[e];
#pragma unroll
        for (int o = 16; o > 0; o >>= 1)
            pv += __shfl_down_sync(0xffffffffu, pv, o);
        if ((u & 31) == 0) vpart[r * 2 + (u >> 5)] = pv;
    }
    CP_WAIT0();
    __syncthreads();

    const __half* wrow = w1h + r * 2560;
    const float* irow = insT + r * 640;
    float acc[4][4];
#pragma unroll
    for (int ii = 0; ii < 4; ii++)
#pragma unroll
        for (int ee = 0; ee < 4; ee++) acc[ii][ee] = 0.f;

#pragma unroll 8
    for (int k = 0; k < 40; k++) {
        uint2 raw = *(const uint2*)&wrow[k * 64 + e0];
        __half2 h01 = *(__half2*)&raw.x;
        __half2 h23 = *(__half2*)&raw.y;
        float2 f01 = __half22float2(h01);
        float2 f23 = __half22float2(h23);
        float4 iv = *(const float4*)&irow[k * 16 + i0];
        float wa[4] = {f01.x, f01.y, f23.x, f23.y};
        float ia[4] = {iv.x, iv.y, iv.z, iv.w};
#pragma unroll
        for (int ii = 0; ii < 4; ii++)
#pragma unroll
            for (int ee = 0; ee < 4; ee++)
                acc[ii][ee] += ia[ii] * wa[ee];
    }

    float4 bv = *(const float4*)&b1c[r * 64 + e0];
    float4 wfv = *(const float4*)&wfc[r * 64 + e0];
    float ba[4] = {bv.x, bv.y, bv.z, bv.w};
    float wa[4] = {wfv.x, wfv.y, wfv.z, wfv.w};
    float p[4];
#pragma unroll
    for (int ii = 0; ii < 4; ii++) {
        float s = 0.f;
#pragma unroll
        for (int ee = 0; ee < 4; ee++) {
            float h = acc[ii][ee] + ba[ee];
            float hd = h > 0.f ? h : expm1f(h);
            s += hd * wa[ee];
        }
        p[ii] = s;
    }
#pragma unroll
    for (int o = 8; o > 0; o >>= 1)
#pragma unroll
        for (int ii = 0; ii < 4; ii++)
            p[ii] += __shfl_down_sync(0xffffffffu, p[ii], o, 16);
    if (eg == 0) {
#pragma unroll
        for (int ii = 0; ii < 4; ii++)
            yrow[r * 16 + i0 + ii] = p[ii];
    }
    __syncthreads();

    if (tid < 64) {
        int rr = tid >> 4, i = tid & 15;
        int bb = b0 + rr;
        float y = yrow[rr * 16 + i] + vpart[rr * 2] + vpart[rr * 2 + 1] + bv2[0];
        float w = fabsf(y);
        if (w_out) w_out[bb * 16 + i] = w;
        float qp = w * agent_qs[bb * 16 + i];
#pragma unroll
        for (int o = 8; o > 0; o >>= 1)
            qp += __shfl_down_sync(0xffffffffu, qp, o, 16);
        if (i == 0 && q_out) q_out[bb] = qp;
    }
}

// ======================================================================
// launch
// ======================================================================
extern "C" void kernel_launch(void* const* d_in, const int* in_sizes, int n_in,
                              void* d_out, int out_size)
{
    const float* states    = (const float*)d_in[0];
    const float* actions   = (const float*)d_in[1];
    const float* agent_qs  = (const float*)d_in[2];
    const int*   gc        = (const int*)  d_in[4];
    const float* W1a = (const float*)d_in[5];
    const float* b1a = (const float*)d_in[6];
    const float* W1b = (const float*)d_in[7];
    const float* b1b = (const float*)d_in[8];
    const float* Wb  = (const float*)d_in[9];
    const float* bb  = (const float*)d_in[10];
    const float* Wfa = (const float*)d_in[11];
    const float* bfa = (const float*)d_in[12];
    const float* Wfb = (const float*)d_in[13];
    const float* bfb = (const float*)d_in[14];
    const float* Wv1 = (const float*)d_in[15];
    const float* bv1 = (const float*)d_in[16];
    const float* Wv2 = (const float*)d_in[17];
    const float* bv2 = (const float*)d_in[18];

    static bool inited = false;
    if (!inited) {
        cudaFuncSetAttribute(stage1_kernel, cudaFuncAttributeMaxDynamicSharedMemorySize, SMEM_S1);
        cudaFuncSetAttribute(stage2_kernel, cudaFuncAttributeMaxDynamicSharedMemorySize, SMEM_S2);
        cudaFuncSetAttribute(final_kernel, cudaFuncAttributeMaxDynamicSharedMemorySize, FINAL_SMEM);
        inited = true;
    }

    float* out = (float*)d_out;
    float* q_out = nullptr;
    float* w_out = nullptr;
    if (out_size == BATCH + BATCH * NAG)      { q_out = out; w_out = out + BATCH; }
    else if (out_size == BATCH * NAG)         { w_out = out; }
    else if (out_size == BATCH)               { q_out = out; }
    else                                      { q_out = out; w_out = out + BATCH; }

    stage1_kernel<<<S1_TOTAL, 256, SMEM_S1>>>(states, W1a, b1a, Wfa, bfa,
                                              Wb, bb, Wv1, bv1, W1b);
    coal_kernel<<<BATCH, 256>>>(actions, gc);
    stage2_kernel<<<128 + 320, 256, SMEM_S2>>>(b1b, Wfb, bfb);
    final_kernel<<<BATCH / 4, 256, FINAL_SMEM>>>(actions, Wv2, bv2, agent_qs,
                                                 q_out, w_out);
}

// round 16
// speedup vs baseline: 1.2025x; 1.2025x over previous
#include <cuda_runtime.h>
#include <cuda_bf16.h>
#include <cuda_fp16.h>
#include <math.h>
#include <stdint.h>

// Problem constants
#define BATCH 2048      // B*T
#define NAG   16
#define NACT  20
#define DDIM  128
#define NSAMP 32
#define EDIM  64
#define HDIM  256
#define W1N   2560      // E*2*A
#define CATN  640       // 256(h1a)+256(hf)+64(b1)+64(vh)

// ---------------- scratch (device globals) ----------------
__device__ float g_out0[BATCH * CATN];
__device__ __half g_Ahi[BATCH * HDIM];      // h1a fp16
__device__ __half g_Bhi[W1N * HDIM];        // W1b^T fp16
__device__ __half g_w1h[BATCH * W1N];       // |w1| fp16
__device__ float g_wf [BATCH * EDIM];
__device__ float g_coal[BATCH * NAG * NACT];

// ===================== PTX helpers =====================
__device__ __forceinline__ uint32_t smem_to_u32(const void* p) {
    uint32_t a;
    asm("{ .reg .u64 t; cvta.to.shared.u64 t, %1; cvt.u32.u64 %0, t; }" : "=r"(a) : "l"(p));
    return a;
}
#define LDMATRIX_X4(r, a) \
    asm volatile("ldmatrix.sync.aligned.m8n8.x4.shared.b16 {%0,%1,%2,%3}, [%4];" \
        : "=r"((r)[0]), "=r"((r)[1]), "=r"((r)[2]), "=r"((r)[3]) : "r"(a))
#define MMA16816H(c, a, b0, b1) \
    asm volatile("mma.sync.aligned.m16n8k16.row.col.f32.f16.f16.f32 " \
        "{%0,%1,%2,%3},{%4,%5,%6,%7},{%8,%9},{%0,%1,%2,%3};" \
        : "+f"((c)[0]), "+f"((c)[1]), "+f"((c)[2]), "+f"((c)[3]) \
        : "r"((a)[0]), "r"((a)[1]), "r"((a)[2]), "r"((a)[3]), "r"(b0), "r"(b1))
#define CP_ASYNC16(dst, src) \
    asm volatile("cp.async.cg.shared.global [%0], [%1], 16;" :: "r"(dst), "l"(src))
#define CP_COMMIT() asm volatile("cp.async.commit_group;" ::: "memory")
#define CP_WAIT1()  asm volatile("cp.async.wait_group 1;" ::: "memory")
#define CP_WAIT0()  asm volatile("cp.async.wait_group 0;" ::: "memory")

// ======================================================================
// STAGE 1: gemm0 (320) + trans_split (640), 66 KB dynamic smem
// ======================================================================
#define S1_GEMM0_BLKS 320
#define S1_TRANS_BLKS 640
#define S1_TOTAL (S1_GEMM0_BLKS + S1_TRANS_BLKS)
#define SMEM_S1  66560

__device__ __forceinline__ void gemm0_block(
    int bx, char* smraw, const float* __restrict__ states,
    const float* __restrict__ W1a, const float* __restrict__ b1a,
    const float* __restrict__ Wfa, const float* __restrict__ bfa,
    const float* __restrict__ Wb,  const float* __restrict__ bb,
    const float* __restrict__ Wv1, const float* __restrict__ bv1)
{
    float* As = (float*)smraw;                   // [64][132]
    float* Bs = (float*)(smraw + 33792);         // [128][64]

    const int tid = threadIdx.x;
    const int n0 = (bx % 10) * 64;
    const int m0 = (bx / 10) * 64;
    const int tx = tid & 15, ty = tid >> 4;

    const float* Bsrc; const float* bias; int ldb; int nc0;
    if      (n0 < 256) { Bsrc = W1a; bias = b1a; ldb = 256; nc0 = n0; }
    else if (n0 < 512) { Bsrc = Wfa; bias = bfa; ldb = 256; nc0 = n0 - 256; }
    else if (n0 < 576) { Bsrc = Wb;  bias = bb;  ldb = 64;  nc0 = 0; }
    else               { Bsrc = Wv1; bias = bv1; ldb = 64;  nc0 = 0; }

#pragma unroll
    for (int j = 0; j < 8; j++) {
        int idx = tid + j * 256;
        int k = idx >> 4, c = idx & 15;
        CP_ASYNC16(smem_to_u32(&Bs[k * 64 + c * 4]),
                   Bsrc + (size_t)k * ldb + nc0 + c * 4);
    }
    CP_COMMIT();

#pragma unroll
    for (int j = 0; j < 8; j++) {
        int idx = tid + j * 256;
        int kg = idx & 31, m = idx >> 5;
        float4 v = *(const float4*)(states + (size_t)(m0 + m) * DDIM + kg * 4);
        *(float4*)&As[m * 132 + kg * 4] = v;
    }
    CP_WAIT0();
    __syncthreads();

    float acc[4][4];
#pragma unroll
    for (int r = 0; r < 4; r++)
#pragma unroll
        for (int j = 0; j < 4; j++) acc[r][j] = 0.f;

#pragma unroll 8
    for (int kk = 0; kk < 128; kk++) {
        float av[4];
#pragma unroll
        for (int r = 0; r < 4; r++) av[r] = As[(ty * 4 + r) * 132 + kk];
        float4 bv = *(const float4*)&Bs[kk * 64 + tx * 4];
        float bw[4] = {bv.x, bv.y, bv.z, bv.w};
#pragma unroll
        for (int r = 0; r < 4; r++)
#pragma unroll
            for (int j = 0; j < 4; j++)
                acc[r][j] += av[r] * bw[j];
    }

    const bool do_relu = (n0 != 512);
    float bs[4];
#pragma unroll
    for (int j = 0; j < 4; j++) bs[j] = bias[nc0 + tx * 4 + j];

#pragma unroll
    for (int r = 0; r < 4; r++) {
        int m = m0 + ty * 4 + r;
        float4 o;
        float* po = &o.x;
#pragma unroll
        for (int j = 0; j < 4; j++) {
            float v = acc[r][j] + bs[j];
            if (do_relu) v = fmaxf(v, 0.f);
            po[j] = v;
        }
        *(float4*)&g_out0[(size_t)m * CATN + n0 + tx * 4] = o;
        if (n0 < 256) {
            size_t base = (size_t)m * HDIM + n0 + tx * 4;
            *(__half2*)&g_Ahi[base]     = __floats2half2_rn(po[0], po[1]);
            *(__half2*)&g_Ahi[base + 2] = __floats2half2_rn(po[2], po[3]);
        }
    }
}

__device__ __forceinline__ void trans_block(int t, char* smraw, const float* __restrict__ W1b)
{
    float* ts = (float*)smraw;      // [32][33]
    int n0 = (t % 80) * 32, k0 = (t / 80) * 32;
    int tx = threadIdx.x & 31, ty = threadIdx.x >> 5;
#pragma unroll
    for (int r = 0; r < 4; r++)
        ts[(ty * 4 + r) * 33 + tx] = W1b[(size_t)(k0 + ty * 4 + r) * W1N + n0 + tx];
    __syncthreads();
#pragma unroll
    for (int r = 0; r < 4; r++) {
        int n = n0 + ty * 4 + r, k = k0 + tx;
        g_Bhi[(size_t)n * HDIM + k] = __float2half(ts[tx * 33 + ty * 4 + r]);
    }
}

__global__ void __launch_bounds__(256)
stage1_kernel(const float* __restrict__ states,
              const float* __restrict__ W1a, const float* __restrict__ b1a,
              const float* __restrict__ Wfa, const float* __restrict__ bfa,
              const float* __restrict__ Wb,  const float* __restrict__ bb,
              const float* __restrict__ Wv1, const float* __restrict__ bv1,
              const float* __restrict__ W1b)
{
    extern __shared__ __align__(16) char smd[];
    const int bx = blockIdx.x;
    if (bx < S1_GEMM0_BLKS)
        gemm0_block(bx, smd, states, W1a, b1a, Wfa, bfa, Wb, bb, Wv1, bv1);
    else
        trans_block(bx - S1_GEMM0_BLKS, smd, W1b);
}

// ======================================================================
// coal standalone (small smem, high occupancy)
// ======================================================================
__global__ void __launch_bounds__(256)
coal_kernel(const float* __restrict__ actions, const int* __restrict__ gc)
{
    __shared__ int   gcs[NSAMP * NAG];
    __shared__ int   inv[NSAMP * NAG];
    __shared__ float act_s[NAG * NACT];
    __shared__ float Ws[NAG * NAG];

    const int b = blockIdx.x;
    const int tid = threadIdx.x;

    for (int idx = tid; idx < 512; idx += 256)
        gcs[idx] = gc[b * 512 + idx];
    for (int idx = tid; idx < 320; idx += 256)
        act_s[idx] = actions[b * 320 + idx];
    __syncthreads();

    {
        int s = tid >> 4, pos = tid & 15;
        inv[s * 16 + gcs[s * 16 + pos]] = pos;
        inv[(s + 16) * 16 + gcs[(s + 16) * 16 + pos]] = pos;
    }
    __syncthreads();

    {
        int i = tid >> 4, m = tid & 15;
        int w = 0;
#pragma unroll
        for (int s = 0; s < 32; s++) {
            int gi = gcs[s * 16 + i];
            int pm = inv[s * 16 + m];
            w += (pm < gi) ? gi : 0;
        }
        Ws[i * 16 + m] = (float)w;
    }
    __syncthreads();

    {
        int i = tid >> 4, c = tid & 15;
        for (int a = c; a < NACT; a += 16) {
            float sum = 0.f;
#pragma unroll
            for (int m = 0; m < 16; m++)
                sum += Ws[i * 16 + m] * act_s[m * NACT + a];
            g_coal[b * 320 + i * NACT + a] = sum * (1.f / 512.f);
        }
    }
}

// ======================================================================
// STAGE 2: wf (128, first) + hmma 128x128 (320 blocks), fp16 1-product
// ======================================================================
#define T_ROWB   80
#define T_BYTES  (128 * T_ROWB)
#define STAGE_B  (2 * T_BYTES)    // Ah, Bh -> 20480
#define SMEM_S2  (2 * STAGE_B)    // 40960

__device__ __forceinline__ void hmma_block(int bx, char* sm, const float* __restrict__ b1b)
{
    const int tid = threadIdx.x;
    const int wid = tid >> 5, lane = tid & 31;
    const int n0 = (bx % 20) * 128;
    const int m0 = (bx / 20) * 128;
    const int wm = (wid >> 2) * 64;
    const int wn = (wid & 3) * 32;

    float acc[4][4][4];
#pragma unroll
    for (int r = 0; r < 4; r++)
#pragma unroll
        for (int g = 0; g < 4; g++)
#pragma unroll
            for (int c = 0; c < 4; c++) acc[r][g][c] = 0.f;

    const __half* srcs[2] = {g_Ahi, g_Bhi};

    auto load_stage = [&](int s, int k0) {
#pragma unroll
        for (int t = 0; t < 2; t++) {
            const int r0 = (t < 1) ? m0 : n0;
            const __half* src = srcs[t];
            char* dstb = sm + s * STAGE_B + t * T_BYTES;
#pragma unroll
            for (int j = 0; j < 2; j++) {
                int idx = tid + j * 256;
                int row = idx >> 2, c = idx & 3;
                CP_ASYNC16(smem_to_u32(dstb + row * T_ROWB + c * 16),
                           (const char*)(src + (size_t)(r0 + row) * HDIM + k0) + c * 16);
            }
        }
    };

    load_stage(0, 0);
    CP_COMMIT();

    for (int kc = 0; kc < 8; kc++) {
        if (kc < 7) { load_stage((kc + 1) & 1, (kc + 1) * 32); CP_COMMIT(); CP_WAIT1(); }
        else        { CP_WAIT0(); }
        __syncthreads();

        char* Ah = sm + (kc & 1) * STAGE_B;
        char* Bh = Ah + T_BYTES;

#pragma unroll
        for (int ks = 0; ks < 2; ks++) {
            const int kb = ks * 32;
            uint32_t ah[4][4], bh[2][4];
            const int arow = wm + (lane & 15);
            const int akb  = kb + (lane >> 4) * 16;
#pragma unroll
            for (int r = 0; r < 4; r++) {
                LDMATRIX_X4(ah[r], smem_to_u32(Ah + (arow + r * 16) * T_ROWB + akb));
            }
            const int brow = wn + (lane & 7) + (lane >> 4) * 8;
            const int bkb  = kb + ((lane >> 3) & 1) * 16;
#pragma unroll
            for (int g = 0; g < 2; g++) {
                LDMATRIX_X4(bh[g], smem_to_u32(Bh + (brow + g * 16) * T_ROWB + bkb));
            }
#pragma unroll
            for (int r = 0; r < 4; r++)
#pragma unroll
                for (int g = 0; g < 4; g++) {
                    uint32_t b0h = bh[g >> 1][(g & 1) * 2], b1h = bh[g >> 1][(g & 1) * 2 + 1];
                    MMA16816H(acc[r][g], ah[r], b0h, b1h);
                }
        }
        __syncthreads();
    }

    const int mrow  = m0 + wm + (lane >> 2);
    const int ncol0 = n0 + wn + (lane & 3) * 2;
#pragma unroll
    for (int g = 0; g < 4; g++) {
        const int n = ncol0 + g * 8;
        float2 bias = *(const float2*)&b1b[n];
#pragma unroll
        for (int r = 0; r < 4; r++) {
            const int m = mrow + r * 16;
            __half2 o0 = __floats2half2_rn(fabsf(acc[r][g][0] + bias.x),
                                           fabsf(acc[r][g][1] + bias.y));
            __half2 o1 = __floats2half2_rn(fabsf(acc[r][g][2] + bias.x),
                                           fabsf(acc[r][g][3] + bias.y));
            *(__half2*)&g_w1h[(size_t)m * W1N + n]       = o0;
            *(__half2*)&g_w1h[(size_t)(m + 8) * W1N + n] = o1;
        }
    }
}

__device__ __forceinline__ void wf_block(int wb, char* sm,
    const float* __restrict__ Wfb, const float* __restrict__ bfb)
{
    float* As = (float*)sm;             // [2][16][36]
    float* Bs = (float*)(sm + 4608);    // [2][32][64]
    const int tid = threadIdx.x;
    const int m0 = wb * 16;
    const int tx = tid & 15, ty = tid >> 4;

    auto load_stage = [&](int s, int k0) {
        if (tid < 128) {
            int row = tid >> 3, c = tid & 7;
            CP_ASYNC16(smem_to_u32(&As[s * 576 + row * 36 + c * 4]),
                       g_out0 + (size_t)(m0 + row) * CATN + 256 + k0 + c * 4);
        }
#pragma unroll
        for (int j = 0; j < 2; j++) {
            int idx = tid * 2 + j;
            int k = idx >> 4, c = idx & 15;
            CP_ASYNC16(smem_to_u32(&Bs[s * 2048 + k * 64 + c * 4]),
                       Wfb + (size_t)(k0 + k) * EDIM + c * 4);
        }
    };

    float acc[4] = {0.f, 0.f, 0.f, 0.f};
    load_stage(0, 0);
    CP_COMMIT();

    for (int c = 0; c < 8; c++) {
        if (c < 7) { load_stage((c + 1) & 1, (c + 1) * 32); CP_COMMIT(); CP_WAIT1(); }
        else       { CP_WAIT0(); }
        __syncthreads();
        const int buf = c & 1;
#pragma unroll
        for (int kk = 0; kk < 32; kk++) {
            float a = As[buf * 576 + ty * 36 + kk];
            float4 bv = *(const float4*)&Bs[buf * 2048 + kk * 64 + tx * 4];
            acc[0] += a * bv.x; acc[1] += a * bv.y;
            acc[2] += a * bv.z; acc[3] += a * bv.w;
        }
        __syncthreads();
    }

    float4 bsv = *(const float4*)&bfb[tx * 4];
    float4 o;
    o.x = fabsf(acc[0] + bsv.x);
    o.y = fabsf(acc[1] + bsv.y);
    o.z = fabsf(acc[2] + bsv.z);
    o.w = fabsf(acc[3] + bsv.w);
    *(float4*)&g_wf[(size_t)(m0 + ty) * EDIM + tx * 4] = o;
}

__global__ void __launch_bounds__(256)
stage2_kernel(const float* __restrict__ b1b,
              const float* __restrict__ Wfb, const float* __restrict__ bfb)
{
    extern __shared__ char sm[];
    const int bx = blockIdx.x;
    if (bx < 128) wf_block(bx, sm, Wfb, bfb);
    else          hmma_block(bx - 128, sm, b1b);
}

// ======================================================================
// STAGE 3: final mix, register-tiled, 4 rows/block, w1 in fp16 smem
// ======================================================================
#define FS_W1    0
#define FS_INST  5120     // [4][40][16]
#define FS_B1    7680     // [4][64]
#define FS_WF    7936     // [4][64]
#define FS_VP    8192     // [4][2]
#define FS_YROW  8200     // [4][16]
#define FINAL_SMEM ((8264 + 24) * 4)   // 33152 bytes

__global__ void __launch_bounds__(256)
final_kernel(const float* __restrict__ actions, const float* __restrict__ Wv2,
             const float* __restrict__ bv2, const float* __restrict__ agent_qs,
             float* __restrict__ q_out, float* __restrict__ w_out)
{
    extern __shared__ __align__(16) float fs[];
    __half* w1h  = (__half*)(fs + FS_W1);
    float* insT = fs + FS_INST;
    float* b1c  = fs + FS_B1;
    float* wfc  = fs + FS_WF;
    float* vpart= fs + FS_VP;
    float* yrow = fs + FS_YROW;

    const int tid = threadIdx.x;
    const int b0 = blockIdx.x * 4;

    {
        const __half* src0 = g_w1h + (size_t)b0 * W1N;
#pragma unroll
        for (int j = 0; j < 5; j++) {
            int idx = tid + j * 256;
            CP_ASYNC16(smem_to_u32((char*)w1h + idx * 16), (const char*)src0 + idx * 16);
        }
        CP_COMMIT();
    }

    const int r  = tid >> 6;
    const int u  = tid & 63;
    const int ig = u >> 4;
    const int eg = u & 15;
    const int i0 = ig * 4, e0 = eg * 4;

#pragma unroll
    for (int j = 0; j < 10; j++) {
        int idx = tid + j * 256;
        int rr = idx / 640, rem = idx % 640;
        int k = rem >> 4, i = rem & 15;
        int bb = b0 + rr;
        float v = (k < 20) ? g_coal[bb * 320 + i * 20 + k]
                           : actions[bb * 320 + i * 20 + (k - 20)];
        insT[rr * 640 + k * 16 + i] = v;
    }
    {
        const int brow = b0 + r;
        int e = u;
        b1c[r * 64 + e] = g_out0[(size_t)brow * CATN + 512 + e];
        wfc[r * 64 + e] = g_wf[(size_t)brow * EDIM + e];
        float pv = g_out0[(size_t)brow * CATN + 576 + e] * Wv2[e];
#pragma unroll
        for (int o = 16; o > 0; o >>= 1)
            pv += __shfl_down_sync(0xffffffffu, pv, o);
        if ((u & 31) == 0) vpart[r * 2 + (u >> 5)] = pv;
    }
    CP_WAIT0();
    __syncthreads();

    const __half* wrow = w1h + r * 2560;
    const float* irow = insT + r * 640;
    float acc[4][4];
#pragma unroll
    for (int ii = 0; ii < 4; ii++)
#pragma unroll
        for (int ee = 0; ee < 4; ee++) acc[ii][ee] = 0.f;

#pragma unroll 8
    for (int k = 0; k < 40; k++) {
        uint2 raw = *(const uint2*)&wrow[k * 64 + e0];
        __half2 h01 = *(__half2*)&raw.x;
        __half2 h23 = *(__half2*)&raw.y;
        float2 f01 = __half22float2(h01);
        float2 f23 = __half22float2(h23);
        float4 iv = *(const float4*)&irow[k * 16 + i0];
        float wa[4] = {f01.x, f01.y, f23.x, f23.y};
        float ia[4] = {iv.x, iv.y, iv.z, iv.w};
#pragma unroll
        for (int ii = 0; ii < 4; ii++)
#pragma unroll
            for (int ee = 0; ee < 4; ee++)
                acc[ii][ee] += ia[ii] * wa[ee];
    }

    float4 bv = *(const float4*)&b1c[r * 64 + e0];
    float4 wfv = *(const float4*)&wfc[r * 64 + e0];
    float ba[4] = {bv.x, bv.y, bv.z, bv.w};
    float wa[4] = {wfv.x, wfv.y, wfv.z, wfv.w};
    float p[4];
#pragma unroll
    for (int ii = 0; ii < 4; ii++) {
        float s = 0.f;
#pragma unroll
        for (int ee = 0; ee < 4; ee++) {
            float h = acc[ii][ee] + ba[ee];
            float hd = h > 0.f ? h : expm1f(h);
            s += hd * wa[ee];
        }
        p[ii] = s;
    }
#pragma unroll
    for (int o = 8; o > 0; o >>= 1)
#pragma unroll
        for (int ii = 0; ii < 4; ii++)
            p[ii] += __shfl_down_sync(0xffffffffu, p[ii], o, 16);
    if (eg == 0) {
#pragma unroll
        for (int ii = 0; ii < 4; ii++)
            yrow[r * 16 + i0 + ii] = p[ii];
    }
    __syncthreads();

    if (tid < 64) {
        int rr = tid >> 4, i = tid & 15;
        int bb = b0 + rr;
        float y = yrow[rr * 16 + i] + vpart[rr * 2] + vpart[rr * 2 + 1] + bv2[0];
        float w = fabsf(y);
        if (w_out) w_out[bb * 16 + i] = w;
        float qp = w * agent_qs[bb * 16 + i];
#pragma unroll
        for (int o = 8; o > 0; o >>= 1)
            qp += __shfl_down_sync(0xffffffffu, qp, o, 16);
        if (i == 0 && q_out) q_out[bb] = qp;
    }
}

// ======================================================================
// launch
// ======================================================================
extern "C" void kernel_launch(void* const* d_in, const int* in_sizes, int n_in,
                              void* d_out, int out_size)
{
    const float* states    = (const float*)d_in[0];
    const float* actions   = (const float*)d_in[1];
    const float* agent_qs  = (const float*)d_in[2];
    const int*   gc        = (const int*)  d_in[4];
    const float* W1a = (const float*)d_in[5];
    const float* b1a = (const float*)d_in[6];
    const float* W1b = (const float*)d_in[7];
    const float* b1b = (const float*)d_in[8];
    const float* Wb  = (const float*)d_in[9];
    const float* bb  = (const float*)d_in[10];
    const float* Wfa = (const float*)d_in[11];
    const float* bfa = (const float*)d_in[12];
    const float* Wfb = (const float*)d_in[13];
    const float* bfb = (const float*)d_in[14];
    const float* Wv1 = (const float*)d_in[15];
    const float* bv1 = (const float*)d_in[16];
    const float* Wv2 = (const float*)d_in[17];
    const float* bv2 = (const float*)d_in[18];

    static bool inited = false;
    if (!inited) {
        cudaFuncSetAttribute(stage1_kernel, cudaFuncAttributeMaxDynamicSharedMemorySize, SMEM_S1);
        cudaFuncSetAttribute(stage2_kernel, cudaFuncAttributeMaxDynamicSharedMemorySize, SMEM_S2);
        cudaFuncSetAttribute(final_kernel, cudaFuncAttributeMaxDynamicSharedMemorySize, FINAL_SMEM);
        inited = true;
    }

    float* out = (float*)d_out;
    float* q_out = nullptr;
    float* w_out = nullptr;
    if (out_size == BATCH + BATCH * NAG)      { q_out = out; w_out = out + BATCH; }
    else if (out_size == BATCH * NAG)         { w_out = out; }
    else if (out_size == BATCH)               { q_out = out; }
    else                                      { q_out = out; w_out = out + BATCH; }

    stage1_kernel<<<S1_TOTAL, 256, SMEM_S1>>>(states, W1a, b1a, Wfa, bfa,
                                              Wb, bb, Wv1, bv1, W1b);
    coal_kernel<<<BATCH, 256>>>(actions, gc);
    stage2_kernel<<<128 + 320, 256, SMEM_S2>>>(b1b, Wfb, bfb);
    final_kernel<<<BATCH / 4, 256, FINAL_SMEM>>>(actions, Wv2, bv2, agent_qs,
                                                 q_out, w_out);
}

// round 17
// speedup vs baseline: 1.3119x; 1.0910x over previous
#include <cuda_runtime.h>
#include <cuda_bf16.h>
#include <cuda_fp16.h>
#include <math.h>
#include <stdint.h>

// Problem constants
#define BATCH 2048      // B*T
#define NAG   16
#define NACT  20
#define DDIM  128
#define NSAMP 32
#define EDIM  64
#define HDIM  256
#define W1N   2560      // E*2*A
#define CATN  640       // 256(h1a)+256(hf)+64(b1)+64(vh)

// ---------------- scratch (device globals) ----------------
__device__ float g_out0[BATCH * CATN];
__device__ __half g_states_h[BATCH * DDIM];   // states fp16
__device__ __half g_wcatT_h[CATN * DDIM];     // [W1a|Wfa|Wb|Wv1]^T fp16 (n-major)
__device__ __half g_Ahi[BATCH * HDIM];        // h1a fp16
__device__ __half g_Bhi[W1N * HDIM];          // W1b^T fp16
__device__ __half g_w1h[BATCH * W1N];         // |w1| fp16
__device__ float g_wf [BATCH * EDIM];
__device__ float g_coal[BATCH * NAG * NACT];

// ===================== PTX helpers =====================
__device__ __forceinline__ uint32_t smem_to_u32(const void* p) {
    uint32_t a;
    asm("{ .reg .u64 t; cvta.to.shared.u64 t, %1; cvt.u32.u64 %0, t; }" : "=r"(a) : "l"(p));
    return a;
}
#define LDMATRIX_X4(r, a) \
    asm volatile("ldmatrix.sync.aligned.m8n8.x4.shared.b16 {%0,%1,%2,%3}, [%4];" \
        : "=r"((r)[0]), "=r"((r)[1]), "=r"((r)[2]), "=r"((r)[3]) : "r"(a))
#define MMA16816H(c, a, b0, b1) \
    asm volatile("mma.sync.aligned.m16n8k16.row.col.f32.f16.f16.f32 " \
        "{%0,%1,%2,%3},{%4,%5,%6,%7},{%8,%9},{%0,%1,%2,%3};" \
        : "+f"((c)[0]), "+f"((c)[1]), "+f"((c)[2]), "+f"((c)[3]) \
        : "r"((a)[0]), "r"((a)[1]), "r"((a)[2]), "r"((a)[3]), "r"(b0), "r"(b1))
#define CP_ASYNC16(dst, src) \
    asm volatile("cp.async.cg.shared.global [%0], [%1], 16;" :: "r"(dst), "l"(src))
#define CP_COMMIT() asm volatile("cp.async.commit_group;" ::: "memory")
#define CP_WAIT1()  asm volatile("cp.async.wait_group 1;" ::: "memory")
#define CP_WAIT0()  asm volatile("cp.async.wait_group 0;" ::: "memory")

// ======================================================================
// PREP: coal (2048) + trans->Bhi (640) + states fp16 (128) + wcatT (40)
// ======================================================================
#define P_COAL   2048
#define P_TRANS  640
#define P_SSPL   128
#define P_WCAT   40
#define P_TOTAL  (P_COAL + P_TRANS + P_SSPL + P_WCAT)

__global__ void __launch_bounds__(256)
prep_kernel(const float* __restrict__ actions, const int* __restrict__ gc,
            const float* __restrict__ W1b, const float* __restrict__ states,
            const float* __restrict__ W1a, const float* __restrict__ Wfa,
            const float* __restrict__ Wb,  const float* __restrict__ Wv1)
{
    __shared__ __align__(16) char psm[6400];
    const int bx = blockIdx.x;
    const int tid = threadIdx.x;

    if (bx < P_COAL) {
        // ---- coal: exact integer weight-matrix formulation ----
        int*   gcs   = (int*)psm;                 // 512 ints
        int*   inv   = gcs + 512;                 // 512 ints
        float* act_s = (float*)(inv + 512);       // 320 floats
        float* Ws    = act_s + 320;               // 256 floats
        const int b = bx;

        for (int idx = tid; idx < 512; idx += 256)
            gcs[idx] = gc[b * 512 + idx];
        for (int idx = tid; idx < 320; idx += 256)
            act_s[idx] = actions[b * 320 + idx];
        __syncthreads();
        {
            int s = tid >> 4, pos = tid & 15;
            inv[s * 16 + gcs[s * 16 + pos]] = pos;
            inv[(s + 16) * 16 + gcs[(s + 16) * 16 + pos]] = pos;
        }
        __syncthreads();
        {
            int i = tid >> 4, m = tid & 15;
            int w = 0;
#pragma unroll
            for (int s = 0; s < 32; s++) {
                int gi = gcs[s * 16 + i];
                int pm = inv[s * 16 + m];
                w += (pm < gi) ? gi : 0;
            }
            Ws[i * 16 + m] = (float)w;
        }
        __syncthreads();
        {
            int i = tid >> 4, c = tid & 15;
            for (int a = c; a < NACT; a += 16) {
                float sum = 0.f;
#pragma unroll
                for (int m = 0; m < 16; m++)
                    sum += Ws[i * 16 + m] * act_s[m * NACT + a];
                g_coal[b * 320 + i * NACT + a] = sum * (1.f / 512.f);
            }
        }
    } else if (bx < P_COAL + P_TRANS) {
        // ---- trans: W1b [256x2560] -> g_Bhi fp16 [2560x256] ----
        float* ts = (float*)psm;       // [32][33]
        const int t = bx - P_COAL;
        int n0 = (t % 80) * 32, k0 = (t / 80) * 32;
        int tx = tid & 31, ty = tid >> 5;
#pragma unroll
        for (int r = 0; r < 4; r++)
            ts[(ty * 4 + r) * 33 + tx] = W1b[(size_t)(k0 + ty * 4 + r) * W1N + n0 + tx];
        __syncthreads();
#pragma unroll
        for (int r = 0; r < 4; r++) {
            int n = n0 + ty * 4 + r, k = k0 + tx;
            g_Bhi[(size_t)n * HDIM + k] = __float2half(ts[tx * 33 + ty * 4 + r]);
        }
    } else if (bx < P_COAL + P_TRANS + P_SSPL) {
        // ---- states -> fp16 ----
        const int base = (bx - P_COAL - P_TRANS) * 2048;
#pragma unroll
        for (int j = 0; j < 8; j++) {
            int i = base + tid + j * 256;
            g_states_h[i] = __float2half(states[i]);
        }
    } else {
        // ---- wcatT fp16: [640][128] ----
        const int base = (bx - P_COAL - P_TRANS - P_SSPL) * 2048;
#pragma unroll
        for (int j = 0; j < 8; j++) {
            int idx = base + tid + j * 256;
            int n = idx >> 7, k = idx & 127;
            float v;
            if      (n < 256) v = W1a[k * 256 + n];
            else if (n < 512) v = Wfa[k * 256 + (n - 256)];
            else if (n < 576) v = Wb [k * 64  + (n - 512)];
            else              v = Wv1[k * 64  + (n - 576)];
            g_wcatT_h[idx] = __float2half(v);
        }
    }
}

// ======================================================================
// GEMM0H: states_h[2048x128] @ WcatT^T -> g_out0 (+ g_Ahi for n<256)
// 128x64 tiles, 160 blocks, single-product fp16 HMMA
// ======================================================================
#define G0_ROWB   80
#define G0_ABYTES (128 * G0_ROWB)   // 10240
#define G0_BBYTES (64 * G0_ROWB)    // 5120
#define G0_STAGE  (G0_ABYTES + G0_BBYTES)   // 15360
#define SMEM_G0   (2 * G0_STAGE)    // 30720

__global__ void __launch_bounds__(256)
gemm0h_kernel(const float* __restrict__ b1a, const float* __restrict__ bfa,
              const float* __restrict__ bb,  const float* __restrict__ bv1)
{
    extern __shared__ char sm[];
    const int tid = threadIdx.x;
    const int wid = tid >> 5, lane = tid & 31;
    const int n0 = (blockIdx.x % 10) * 64;
    const int m0 = (blockIdx.x / 10) * 128;
    const int wm = (wid >> 1) * 32;     // 4 row groups
    const int wn = (wid & 1) * 32;      // 2 col groups

    float acc[2][4][4];
#pragma unroll
    for (int r = 0; r < 2; r++)
#pragma unroll
        for (int g = 0; g < 4; g++)
#pragma unroll
            for (int c = 0; c < 4; c++) acc[r][g][c] = 0.f;

    auto load_stage = [&](int s, int k0) {
        char* base = sm + s * G0_STAGE;
        // A: 128 rows x 32 halfs (64B) = 512 chunks, 2/thread
#pragma unroll
        for (int j = 0; j < 2; j++) {
            int idx = tid + j * 256;
            int row = idx >> 2, c = idx & 3;
            CP_ASYNC16(smem_to_u32(base + row * G0_ROWB + c * 16),
                       (const char*)(g_states_h + (size_t)(m0 + row) * DDIM + k0) + c * 16);
        }
        // B: 64 rows x 32 halfs = 256 chunks, 1/thread
        {
            int row = tid >> 2, c = tid & 3;
            CP_ASYNC16(smem_to_u32(base + G0_ABYTES + row * G0_ROWB + c * 16),
                       (const char*)(g_wcatT_h + (size_t)(n0 + row) * DDIM + k0) + c * 16);
        }
    };

    load_stage(0, 0);
    CP_COMMIT();

    for (int kc = 0; kc < 4; kc++) {
        if (kc < 3) { load_stage((kc + 1) & 1, (kc + 1) * 32); CP_COMMIT(); CP_WAIT1(); }
        else        { CP_WAIT0(); }
        __syncthreads();

        char* Ah = sm + (kc & 1) * G0_STAGE;
        char* Bh = Ah + G0_ABYTES;

#pragma unroll
        for (int ks = 0; ks < 2; ks++) {
            const int kb = ks * 32;
            uint32_t ah[2][4], bh[2][4];
            const int arow = wm + (lane & 15);
            const int akb  = kb + (lane >> 4) * 16;
#pragma unroll
            for (int r = 0; r < 2; r++)
                LDMATRIX_X4(ah[r], smem_to_u32(Ah + (arow + r * 16) * G0_ROWB + akb));
            const int brow = wn + (lane & 7) + (lane >> 4) * 8;
            const int bkb  = kb + ((lane >> 3) & 1) * 16;
#pragma unroll
            for (int g = 0; g < 2; g++)
                LDMATRIX_X4(bh[g], smem_to_u32(Bh + (brow + g * 16) * G0_ROWB + bkb));
#pragma unroll
            for (int r = 0; r < 2; r++)
#pragma unroll
                for (int g = 0; g < 4; g++) {
                    uint32_t b0 = bh[g >> 1][(g & 1) * 2], b1 = bh[g >> 1][(g & 1) * 2 + 1];
                    MMA16816H(acc[r][g], ah[r], b0, b1);
                }
        }
        __syncthreads();
    }

    // epilogue: region-dependent bias/relu
    const float* biasp; int rbase; bool do_relu;
    if      (n0 < 256) { biasp = b1a; rbase = 0;   do_relu = true; }
    else if (n0 < 512) { biasp = bfa; rbase = 256; do_relu = true; }
    else if (n0 < 576) { biasp = bb;  rbase = 512; do_relu = false; }
    else               { biasp = bv1; rbase = 576; do_relu = true; }

    const int mrow  = m0 + wm + (lane >> 2);
    const int ncol0 = n0 + wn + (lane & 3) * 2;
#pragma unroll
    for (int g = 0; g < 4; g++) {
        const int n = ncol0 + g * 8;
        float2 bias = *(const float2*)&biasp[n - rbase];
#pragma unroll
        for (int r = 0; r < 2; r++) {
            const int m = mrow + r * 16;
#pragma unroll
            for (int h = 0; h < 2; h++) {
                const int mm = m + h * 8;
                float vx = acc[r][g][h * 2 + 0] + bias.x;
                float vy = acc[r][g][h * 2 + 1] + bias.y;
                if (do_relu) { vx = fmaxf(vx, 0.f); vy = fmaxf(vy, 0.f); }
                *(float2*)&g_out0[(size_t)mm * CATN + n] = make_float2(vx, vy);
                if (n0 < 256)
                    *(__half2*)&g_Ahi[(size_t)mm * HDIM + n] = __floats2half2_rn(vx, vy);
            }
        }
    }
}

// ======================================================================
// STAGE 2: wf (128, first) + hmma 128x128 (320 blocks), fp16 1-product
// ======================================================================
#define T_ROWB   80
#define T_BYTES  (128 * T_ROWB)
#define STAGE_B  (2 * T_BYTES)    // 20480
#define SMEM_S2  (2 * STAGE_B)    // 40960

__device__ __forceinline__ void hmma_block(int bx, char* sm, const float* __restrict__ b1b)
{
    const int tid = threadIdx.x;
    const int wid = tid >> 5, lane = tid & 31;
    const int n0 = (bx % 20) * 128;
    const int m0 = (bx / 20) * 128;
    const int wm = (wid >> 2) * 64;
    const int wn = (wid & 3) * 32;

    float acc[4][4][4];
#pragma unroll
    for (int r = 0; r < 4; r++)
#pragma unroll
        for (int g = 0; g < 4; g++)
#pragma unroll
            for (int c = 0; c < 4; c++) acc[r][g][c] = 0.f;

    const __half* srcs[2] = {g_Ahi, g_Bhi};

    auto load_stage = [&](int s, int k0) {
#pragma unroll
        for (int t = 0; t < 2; t++) {
            const int r0 = (t < 1) ? m0 : n0;
            const __half* src = srcs[t];
            char* dstb = sm + s * STAGE_B + t * T_BYTES;
#pragma unroll
            for (int j = 0; j < 2; j++) {
                int idx = tid + j * 256;
                int row = idx >> 2, c = idx & 3;
                CP_ASYNC16(smem_to_u32(dstb + row * T_ROWB + c * 16),
                           (const char*)(src + (size_t)(r0 + row) * HDIM + k0) + c * 16);
            }
        }
    };

    load_stage(0, 0);
    CP_COMMIT();

    for (int kc = 0; kc < 8; kc++) {
        if (kc < 7) { load_stage((kc + 1) & 1, (kc + 1) * 32); CP_COMMIT(); CP_WAIT1(); }
        else        { CP_WAIT0(); }
        __syncthreads();

        char* Ah = sm + (kc & 1) * STAGE_B;
        char* Bh = Ah + T_BYTES;

#pragma unroll
        for (int ks = 0; ks < 2; ks++) {
            const int kb = ks * 32;
            uint32_t ah[4][4], bh[2][4];
            const int arow = wm + (lane & 15);
            const int akb  = kb + (lane >> 4) * 16;
#pragma unroll
            for (int r = 0; r < 4; r++)
                LDMATRIX_X4(ah[r], smem_to_u32(Ah + (arow + r * 16) * T_ROWB + akb));
            const int brow = wn + (lane & 7) + (lane >> 4) * 8;
            const int bkb  = kb + ((lane >> 3) & 1) * 16;
#pragma unroll
            for (int g = 0; g < 2; g++)
                LDMATRIX_X4(bh[g], smem_to_u32(Bh + (brow + g * 16) * T_ROWB + bkb));
#pragma unroll
            for (int r = 0; r < 4; r++)
#pragma unroll
                for (int g = 0; g < 4; g++) {
                    uint32_t b0h = bh[g >> 1][(g & 1) * 2], b1h = bh[g >> 1][(g & 1) * 2 + 1];
                    MMA16816H(acc[r][g], ah[r], b0h, b1h);
                }
        }
        __syncthreads();
    }

    const int mrow  = m0 + wm + (lane >> 2);
    const int ncol0 = n0 + wn + (lane & 3) * 2;
#pragma unroll
    for (int g = 0; g < 4; g++) {
        const int n = ncol0 + g * 8;
        float2 bias = *(const float2*)&b1b[n];
#pragma unroll
        for (int r = 0; r < 4; r++) {
            const int m = mrow + r * 16;
            __half2 o0 = __floats2half2_rn(fabsf(acc[r][g][0] + bias.x),
                                           fabsf(acc[r][g][1] + bias.y));
            __half2 o1 = __floats2half2_rn(fabsf(acc[r][g][2] + bias.x),
                                           fabsf(acc[r][g][3] + bias.y));
            *(__half2*)&g_w1h[(size_t)m * W1N + n]       = o0;
            *(__half2*)&g_w1h[(size_t)(m + 8) * W1N + n] = o1;
        }
    }
}

__device__ __forceinline__ void wf_block(int wb, char* sm,
    const float* __restrict__ Wfb, const float* __restrict__ bfb)
{
    float* As = (float*)sm;             // [2][16][36]
    float* Bs = (float*)(sm + 4608);    // [2][32][64]
    const int tid = threadIdx.x;
    const int m0 = wb * 16;
    const int tx = tid & 15, ty = tid >> 4;

    auto load_stage = [&](int s, int k0) {
        if (tid < 128) {
            int row = tid >> 3, c = tid & 7;
            CP_ASYNC16(smem_to_u32(&As[s * 576 + row * 36 + c * 4]),
                       g_out0 + (size_t)(m0 + row) * CATN + 256 + k0 + c * 4);
        }
#pragma unroll
        for (int j = 0; j < 2; j++) {
            int idx = tid * 2 + j;
            int k = idx >> 4, c = idx & 15;
            CP_ASYNC16(smem_to_u32(&Bs[s * 2048 + k * 64 + c * 4]),
                       Wfb + (size_t)(k0 + k) * EDIM + c * 4);
        }
    };

    float acc[4] = {0.f, 0.f, 0.f, 0.f};
    load_stage(0, 0);
    CP_COMMIT();

    for (int c = 0; c < 8; c++) {
        if (c < 7) { load_stage((c + 1) & 1, (c + 1) * 32); CP_COMMIT(); CP_WAIT1(); }
        else       { CP_WAIT0(); }
        __syncthreads();
        const int buf = c & 1;
#pragma unroll
        for (int kk = 0; kk < 32; kk++) {
            float a = As[buf * 576 + ty * 36 + kk];
            float4 bv = *(const float4*)&Bs[buf * 2048 + kk * 64 + tx * 4];
            acc[0] += a * bv.x; acc[1] += a * bv.y;
            acc[2] += a * bv.z; acc[3] += a * bv.w;
        }
        __syncthreads();
    }

    float4 bsv = *(const float4*)&bfb[tx * 4];
    float4 o;
    o.x = fabsf(acc[0] + bsv.x);
    o.y = fabsf(acc[1] + bsv.y);
    o.z = fabsf(acc[2] + bsv.z);
    o.w = fabsf(acc[3] + bsv.w);
    *(float4*)&g_wf[(size_t)(m0 + ty) * EDIM + tx * 4] = o;
}

__global__ void __launch_bounds__(256)
stage2_kernel(const float* __restrict__ b1b,
              const float* __restrict__ Wfb, const float* __restrict__ bfb)
{
    extern __shared__ char sm[];
    const int bx = blockIdx.x;
    if (bx < 128) wf_block(bx, sm, Wfb, bfb);
    else          hmma_block(bx - 128, sm, b1b);
}

// ======================================================================
// STAGE 3: final mix, register-tiled, 4 rows/block, w1 in fp16 smem
// ======================================================================
#define FS_W1    0
#define FS_INST  5120     // [4][40][16]
#define FS_B1    7680     // [4][64]
#define FS_WF    7936     // [4][64]
#define FS_VP    8192     // [4][2]
#define FS_YROW  8200     // [4][16]
#define FINAL_SMEM ((8264 + 24) * 4)   // 33152 bytes

__global__ void __launch_bounds__(256)
final_kernel(const float* __restrict__ actions, const float* __restrict__ Wv2,
             const float* __restrict__ bv2, const float* __restrict__ agent_qs,
             float* __restrict__ q_out, float* __restrict__ w_out)
{
    extern __shared__ __align__(16) float fs[];
    __half* w1h  = (__half*)(fs + FS_W1);
    float* insT = fs + FS_INST;
    float* b1c  = fs + FS_B1;
    float* wfc  = fs + FS_WF;
    float* vpart= fs + FS_VP;
    float* yrow = fs + FS_YROW;

    const int tid = threadIdx.x;
    const int b0 = blockIdx.x * 4;

    {
        const __half* src0 = g_w1h + (size_t)b0 * W1N;
#pragma unroll
        for (int j = 0; j < 5; j++) {
            int idx = tid + j * 256;
            CP_ASYNC16(smem_to_u32((char*)w1h + idx * 16), (const char*)src0 + idx * 16);
        }
        CP_COMMIT();
    }

    const int r  = tid >> 6;
    const int u  = tid & 63;
    const int ig = u >> 4;
    const int eg = u & 15;
    const int i0 = ig * 4, e0 = eg * 4;

#pragma unroll
    for (int j = 0; j < 10; j++) {
        int idx = tid + j * 256;
        int rr = idx / 640, rem = idx % 640;
        int k = rem >> 4, i = rem & 15;
        int bb = b0 + rr;
        float v = (k < 20) ? g_coal[bb * 320 + i * 20 + k]
                           : actions[bb * 320 + i * 20 + (k - 20)];
        insT[rr * 640 + k * 16 + i] = v;
    }
    {
        const int brow = b0 + r;
        int e = u;
        b1c[r * 64 + e] = g_out0[(size_t)brow * CATN + 512 + e];
        wfc[r * 64 + e] = g_wf[(size_t)brow * EDIM + e];
        float pv = g_out0[(size_t)brow * CATN + 576 + e] * Wv2[e];
#pragma unroll
        for (int o = 16; o > 0; o >>= 1)
            pv += __shfl_down_sync(0xffffffffu, pv, o);
        if ((u & 31) == 0) vpart[r * 2 + (u >> 5)] = pv;
    }
    CP_WAIT0();
    __syncthreads();

    const __half* wrow = w1h + r * 2560;
    const float* irow = insT + r * 640;
    float acc[4][4];
#pragma unroll
    for (int ii = 0; ii < 4; ii++)
#pragma unroll
        for (int ee = 0; ee < 4; ee++) acc[ii][ee] = 0.f;

#pragma unroll 8
    for (int k = 0; k < 40; k++) {
        uint2 raw = *(const uint2*)&wrow[k * 64 + e0];
        __half2 h01 = *(__half2*)&raw.x;
        __half2 h23 = *(__half2*)&raw.y;
        float2 f01 = __half22float2(h01);
        float2 f23 = __half22float2(h23);
        float4 iv = *(const float4*)&irow[k * 16 + i0];
        float wa[4] = {f01.x, f01.y, f23.x, f23.y};
        float ia[4] = {iv.x, iv.y, iv.z, iv.w};
#pragma unroll
        for (int ii = 0; ii < 4; ii++)
#pragma unroll
            for (int ee = 0; ee < 4; ee++)
                acc[ii][ee] += ia[ii] * wa[ee];
    }

    float4 bv = *(const float4*)&b1c[r * 64 + e0];
    float4 wfv = *(const float4*)&wfc[r * 64 + e0];
    float ba[4] = {bv.x, bv.y, bv.z, bv.w};
    float wa[4] = {wfv.x, wfv.y, wfv.z, wfv.w};
    float p[4];
#pragma unroll
    for (int ii = 0; ii < 4; ii++) {
        float s = 0.f;
#pragma unroll
        for (int ee = 0; ee < 4; ee++) {
            float h = acc[ii][ee] + ba[ee];
            float hd = h > 0.f ? h : expm1f(h);
            s += hd * wa[ee];
        }
        p[ii] = s;
    }
#pragma unroll
    for (int o = 8; o > 0; o >>= 1)
#pragma unroll
        for (int ii = 0; ii < 4; ii++)
            p[ii] += __shfl_down_sync(0xffffffffu, p[ii], o, 16);
    if (eg == 0) {
#pragma unroll
        for (int ii = 0; ii < 4; ii++)
            yrow[r * 16 + i0 + ii] = p[ii];
    }
    __syncthreads();

    if (tid < 64) {
        int rr = tid >> 4, i = tid & 15;
        int bb = b0 + rr;
        float y = yrow[rr * 16 + i] + vpart[rr * 2] + vpart[rr * 2 + 1] + bv2[0];
        float w = fabsf(y);
        if (w_out) w_out[bb * 16 + i] = w;
        float qp = w * agent_qs[bb * 16 + i];
#pragma unroll
        for (int o = 8; o > 0; o >>= 1)
            qp += __shfl_down_sync(0xffffffffu, qp, o, 16);
        if (i == 0 && q_out) q_out[bb] = qp;
    }
}

// ======================================================================
// launch
// ======================================================================
extern "C" void kernel_launch(void* const* d_in, const int* in_sizes, int n_in,
                              void* d_out, int out_size)
{
    const float* states    = (const float*)d_in[0];
    const float* actions   = (const float*)d_in[1];
    const float* agent_qs  = (const float*)d_in[2];
    const int*   gc        = (const int*)  d_in[4];
    const float* W1a = (const float*)d_in[5];
    const float* b1a = (const float*)d_in[6];
    const float* W1b = (const float*)d_in[7];
    const float* b1b = (const float*)d_in[8];
    const float* Wb  = (const float*)d_in[9];
    const float* bb  = (const float*)d_in[10];
    const float* Wfa = (const float*)d_in[11];
    const float* bfa = (const float*)d_in[12];
    const float* Wfb = (const float*)d_in[13];
    const float* bfb = (const float*)d_in[14];
    const float* Wv1 = (const float*)d_in[15];
    const float* bv1 = (const float*)d_in[16];
    const float* Wv2 = (const float*)d_in[17];
    const float* bv2 = (const float*)d_in[18];

    static bool inited = false;
    if (!inited) {
        cudaFuncSetAttribute(stage2_kernel, cudaFuncAttributeMaxDynamicSharedMemorySize, SMEM_S2);
        cudaFuncSetAttribute(final_kernel, cudaFuncAttributeMaxDynamicSharedMemorySize, FINAL_SMEM);
        inited = true;
    }

    float* out = (float*)d_out;
    float* q_out = nullptr;
    float* w_out = nullptr;
    if (out_size == BATCH + BATCH * NAG)      { q_out = out; w_out = out + BATCH; }
    else if (out_size == BATCH * NAG)         { w_out = out; }
    else if (out_size == BATCH)               { q_out = out; }
    else                                      { q_out = out; w_out = out + BATCH; }

    prep_kernel<<<P_TOTAL, 256>>>(actions, gc, W1b, states, W1a, Wfa, Wb, Wv1);
    gemm0h_kernel<<<160, 256, SMEM_G0>>>(b1a, bfa, bb, bv1);
    stage2_kernel<<<128 + 320, 256, SMEM_S2>>>(b1b, Wfb, bfb);
    final_kernel<<<BATCH / 4, 256, FINAL_SMEM>>>(actions, Wv2, bv2, agent_qs,
                                                 q_out, w_out);
}